// round 13
// baseline (speedup 1.0000x reference)
#include <cuda_runtime.h>
#include <cuda_bf16.h>
#include <cuda_fp16.h>
#include <math_constants.h>
#include <stdint.h>

#define BATCH 4
#define NTOK 4096
#define CIN 256
#define ADIM 128
#define MTOT (BATCH*NTOK)
#define NEG_SLOPE 0.2f
#define LOG2E 1.4426950408889634f

// ---------------- scratch ----------------
__device__ __nv_bfloat16 g_Qh[MTOT * ADIM];   // pre-scaled by log2(e)
__device__ __nv_bfloat16 g_Ql[MTOT * ADIM];
__device__ __nv_bfloat16 g_Kh[MTOT * ADIM];
__device__ __nv_bfloat16 g_Kl[MTOT * ADIM];
__device__ __half        g_V[MTOT * ADIM];
__device__ __nv_bfloat16 g_Oh[MTOT * ADIM];
__device__ __nv_bfloat16 g_Ol[MTOT * ADIM];

__device__ __forceinline__ float lrelu(float x) { return x >= 0.0f ? x : NEG_SLOPE * x; }

// ---------------- helpers ----------------
__device__ __forceinline__ uint32_t smem_u32(const void* p) {
    uint32_t a;
    asm("{ .reg .u64 t; cvta.to.shared.u64 t, %1; cvt.u32.u64 %0, t; }" : "=r"(a) : "l"(p));
    return a;
}
__device__ __forceinline__ void cp16(uint32_t dst, const void* src) {
    asm volatile("cp.async.cg.shared.global [%0], [%1], 16;" :: "r"(dst), "l"(src));
}
__device__ __forceinline__ void cp_commit() { asm volatile("cp.async.commit_group;" ::: "memory"); }
__device__ __forceinline__ void cp_wait0() { asm volatile("cp.async.wait_group 0;" ::: "memory"); }
__device__ __forceinline__ void cp_wait1() { asm volatile("cp.async.wait_group 1;" ::: "memory"); }

__device__ __forceinline__ void ldsm4(uint32_t* r, uint32_t a) {
    asm volatile("ldmatrix.sync.aligned.m8n8.x4.shared.b16 {%0,%1,%2,%3}, [%4];"
        : "=r"(r[0]), "=r"(r[1]), "=r"(r[2]), "=r"(r[3]) : "r"(a));
}
__device__ __forceinline__ void ldsm4t(uint32_t* r, uint32_t a) {
    asm volatile("ldmatrix.sync.aligned.m8n8.x4.trans.shared.b16 {%0,%1,%2,%3}, [%4];"
        : "=r"(r[0]), "=r"(r[1]), "=r"(r[2]), "=r"(r[3]) : "r"(a));
}
__device__ __forceinline__ void mma_bf16(float* d, const uint32_t* a, const uint32_t* b) {
    asm volatile(
        "mma.sync.aligned.m16n8k16.row.col.f32.bf16.bf16.f32 "
        "{%0,%1,%2,%3}, {%4,%5,%6,%7}, {%8,%9}, {%0,%1,%2,%3};"
        : "+f"(d[0]), "+f"(d[1]), "+f"(d[2]), "+f"(d[3])
        : "r"(a[0]), "r"(a[1]), "r"(a[2]), "r"(a[3]), "r"(b[0]), "r"(b[1]));
}
__device__ __forceinline__ void mma_f16(float* d, const uint32_t* a, const uint32_t* b) {
    asm volatile(
        "mma.sync.aligned.m16n8k16.row.col.f32.f16.f16.f32 "
        "{%0,%1,%2,%3}, {%4,%5,%6,%7}, {%8,%9}, {%0,%1,%2,%3};"
        : "+f"(d[0]), "+f"(d[1]), "+f"(d[2]), "+f"(d[3])
        : "r"(a[0]), "r"(a[1]), "r"(a[2]), "r"(a[3]), "r"(b[0]), "r"(b[1]));
}
__device__ __forceinline__ uint32_t h2bits(__half2 v) { return *(uint32_t*)&v; }
__device__ __forceinline__ float ex2(float x) {
    float r; asm("ex2.approx.f32 %0, %1;" : "=f"(r) : "f"(x)); return r;
}

__device__ __forceinline__ void split2(float f0, float f1, __nv_bfloat162& h, __nv_bfloat162& l) {
    h = __floats2bfloat162_rn(f0, f1);
    l = __floats2bfloat162_rn(f0 - __bfloat162float(h.x), f1 - __bfloat162float(h.y));
}
// Convert 8 consecutive fp32 -> 16B hi chunk + 16B lo chunk, store to smem.
__device__ __forceinline__ void split_sts8(const float* src, uint32_t dst_h, uint32_t dst_l) {
    float4 a = *(const float4*)src;
    float4 b = *(const float4*)(src + 4);
    __nv_bfloat162 h0, l0, h1, l1, h2, l2, h3, l3;
    split2(a.x, a.y, h0, l0);
    split2(a.z, a.w, h1, l1);
    split2(b.x, b.y, h2, l2);
    split2(b.z, b.w, h3, l3);
    uint4 hv = make_uint4(*(uint32_t*)&h0, *(uint32_t*)&h1, *(uint32_t*)&h2, *(uint32_t*)&h3);
    uint4 lv = make_uint4(*(uint32_t*)&l0, *(uint32_t*)&l1, *(uint32_t*)&l2, *(uint32_t*)&l3);
    asm volatile("st.shared.v4.b32 [%0], {%1,%2,%3,%4};"
                 :: "r"(dst_h), "r"(hv.x), "r"(hv.y), "r"(hv.z), "r"(hv.w) : "memory");
    asm volatile("st.shared.v4.b32 [%0], {%1,%2,%3,%4};"
                 :: "r"(dst_l), "r"(lv.x), "r"(lv.y), "r"(lv.z), "r"(lv.w) : "memory");
}

// =====================================================================
// Kernel 1: QKV projection via mma.sync, 3xBF16 split.
// grid (128, 3), 256 threads. fp32 X/W prefetched into double-buffered
// smem staging via cp.async, split smem->smem, then MMA.
// smem: split bufs 64K | staging 2 x (X 32K + W 32K) = 192K
// =====================================================================
#define QKV2_XH 0
#define QKV2_XL 16384
#define QKV2_WH 32768
#define QKV2_WL 49152
#define QKV2_STG 65536           // + buf*65536 ; X fp32 at +0 (32K), W fp32 at +32768
#define QKV2_SMEM (65536 + 2*65536)

__global__ __launch_bounds__(256)
void qkv2_kernel(const float* __restrict__ X,
                 const float* __restrict__ Wq,
                 const float* __restrict__ Wk,
                 const float* __restrict__ Wv) {
    extern __shared__ char smc[];
    const uint32_t sb = smem_u32(smc);
    const int tid = threadIdx.x;
    const int w = tid >> 5;
    const int lane = tid & 31;
    const int row0 = blockIdx.x * 128;

    const float* Wsel = (blockIdx.y == 0) ? Wq : (blockIdx.y == 1) ? Wk : Wv;

    const int rowa = 16 * w + (lane & 15);
    const int ca = lane >> 4, swa = rowa & 7;
    const int rowv = (lane & 7) + (lane & 8);
    const int cv = (lane >> 4) & 1, swv = rowv & 7;

    // cp.async a fp32 chunk pair (X[128x64], W[64x128]) into staging buf
    auto stage = [&](int kc, uint32_t stg) {
        // X: 2048 16B-chunks; row = j>>4 (16 chunks/row), col16 = j&15
        #pragma unroll
        for (int i = 0; i < 8; i++) {
            int j = tid + i * 256;
            int r = j >> 4, c16 = j & 15;
            cp16(stg + (uint32_t)j * 16,
                 &X[(size_t)(row0 + r) * CIN + kc * 64 + c16 * 4]);
        }
        // W: 2048 16B-chunks; row = j>>5 (32 chunks/row)
        #pragma unroll
        for (int i = 0; i < 8; i++) {
            int j = tid + i * 256;
            int r = j >> 5, c16 = j & 31;
            cp16(stg + 32768u + (uint32_t)j * 16,
                 &Wsel[(size_t)(kc * 64 + r) * ADIM + c16 * 4]);
        }
    };

    float oacc[16][4];
    #pragma unroll
    for (int nb = 0; nb < 16; nb++)
        #pragma unroll
        for (int i = 0; i < 4; i++) oacc[nb][i] = 0.0f;

    stage(0, sb + QKV2_STG);
    cp_commit();

    #pragma unroll 1
    for (int kc = 0; kc < 4; kc++) {
        if (kc < 3) {
            stage(kc + 1, sb + QKV2_STG + (uint32_t)((kc + 1) & 1) * 65536u);
            cp_commit();
            cp_wait1();
        } else {
            cp_wait0();
        }
        __syncthreads();   // staging(kc) ready; prev MMA done reading split bufs

        const uint32_t stg = sb + QKV2_STG + (uint32_t)(kc & 1) * 65536u;
        const char* stgp = smc + (stg - sb);
        // split X [128 x 64] fp32 -> hi/lo
        #pragma unroll
        for (int i = 0; i < 4; i++) {
            int lin = tid + i * 256;
            int r = lin >> 3, c = lin & 7;
            uint32_t off = (uint32_t)(r * 128 + ((c ^ (r & 7)) << 4));
            split_sts8((const float*)(stgp + r * 256 + c * 32),
                       sb + QKV2_XH + off, sb + QKV2_XL + off);
        }
        // split W [64 x 128]
        #pragma unroll
        for (int i = 0; i < 4; i++) {
            int lin = tid + i * 256;
            int r = lin >> 4, c = lin & 15;
            uint32_t off = (uint32_t)(r * 256 + ((c ^ (r & 7)) << 4));
            split_sts8((const float*)(stgp + 32768 + r * 512 + c * 32),
                       sb + QKV2_WH + off, sb + QKV2_WL + off);
        }
        __syncthreads();

        #pragma unroll
        for (int ks = 0; ks < 4; ks++) {
            uint32_t ah[4], al[4];
            uint32_t ach = (uint32_t)(((2 * ks + ca) ^ swa) << 4);
            ldsm4(ah, sb + QKV2_XH + rowa * 128 + ach);
            ldsm4(al, sb + QKV2_XL + rowa * 128 + ach);
            #pragma unroll
            for (int jp = 0; jp < 8; jp++) {
                uint32_t bh[4], bl[4];
                uint32_t boff = (uint32_t)((16 * ks + rowv) * 256 + (((2 * jp + cv) ^ swv) << 4));
                ldsm4t(bh, sb + QKV2_WH + boff);
                ldsm4t(bl, sb + QKV2_WL + boff);
                mma_bf16(oacc[2 * jp],     ah, bh); mma_bf16(oacc[2 * jp + 1], ah, bh + 2);
                mma_bf16(oacc[2 * jp],     ah, bl); mma_bf16(oacc[2 * jp + 1], ah, bl + 2);
                mma_bf16(oacc[2 * jp],     al, bh); mma_bf16(oacc[2 * jp + 1], al, bh + 2);
            }
        }
    }

    const int r0 = row0 + 16 * w + (lane >> 2);
    const int cb2 = 2 * (lane & 3);
    if (blockIdx.y == 2) {
        #pragma unroll
        for (int nb = 0; nb < 16; nb++) {
            int c = nb * 8 + cb2;
            *(__half2*)&g_V[(size_t)r0 * ADIM + c] =
                __floats2half2_rn(lrelu(oacc[nb][0]), lrelu(oacc[nb][1]));
            *(__half2*)&g_V[(size_t)(r0 + 8) * ADIM + c] =
                __floats2half2_rn(lrelu(oacc[nb][2]), lrelu(oacc[nb][3]));
        }
    } else {
        __nv_bfloat16* OH = (blockIdx.y == 0) ? g_Qh : g_Kh;
        __nv_bfloat16* OL = (blockIdx.y == 0) ? g_Ql : g_Kl;
        const float sc = (blockIdx.y == 0) ? LOG2E : 1.0f;
        #pragma unroll
        for (int nb = 0; nb < 16; nb++) {
            int c = nb * 8 + cb2;
            __nv_bfloat162 h01, l01, h23, l23;
            split2(lrelu(oacc[nb][0]) * sc, lrelu(oacc[nb][1]) * sc, h01, l01);
            split2(lrelu(oacc[nb][2]) * sc, lrelu(oacc[nb][3]) * sc, h23, l23);
            *(__nv_bfloat162*)&OH[(size_t)r0 * ADIM + c] = h01;
            *(__nv_bfloat162*)&OL[(size_t)r0 * ADIM + c] = l01;
            *(__nv_bfloat162*)&OH[(size_t)(r0 + 8) * ADIM + c] = h23;
            *(__nv_bfloat162*)&OL[(size_t)(r0 + 8) * ADIM + c] = l23;
        }
    }
}

// =====================================================================
// Kernel 2: flash attention, software-pipelined with double sacc.
// grid (32,4), 256 threads.  (unchanged from R11/R12)
// =====================================================================
#define SQH 0
#define SQL 32768
#define SKV 65536
#define KVBUF 49152
#define ATTN_SMEM (65536 + 3*KVBUF)

__device__ __forceinline__ void load_kv(uint32_t dst, const __nv_bfloat16* kh,
                                        const __nv_bfloat16* kl, const __half* v, int tid) {
    #pragma unroll
    for (int i = 0; i < 4; i++) {
        int lin = tid + i * 256;
        int r = lin >> 4, c = lin & 15;
        uint32_t off = (uint32_t)(r * 256 + ((c ^ (r & 7)) << 4));
        size_t g = (size_t)r * ADIM + c * 8;
        cp16(dst + off, kh + g);
        cp16(dst + 16384 + off, kl + g);
        cp16(dst + 32768 + off, v + g);
    }
}

__global__ __launch_bounds__(256, 1)
void attn_kernel() {
    extern __shared__ char smc[];
    const uint32_t sb = smem_u32(smc);
    const int tid = threadIdx.x;
    const int w = tid >> 5;
    const int lane = tid & 31;
    const int b = blockIdx.y;
    const int q0 = blockIdx.x * 128;

    const int rowa = 16 * w + (lane & 15);
    const uint32_t qro = (uint32_t)rowa * 256;
    const int ca = lane >> 4;
    const int swa = rowa & 7;
    const int rowb = (lane & 7) + ((lane & 16) >> 1);
    const int cb = (lane >> 3) & 1;
    const int swb = rowb & 7;
    const int rowv = (lane & 7) + (lane & 8);
    const int cv = (lane >> 4) & 1;
    const int swv = rowv & 7;

    {
        const __nv_bfloat16* qh = g_Qh + (size_t)(b * NTOK + q0) * ADIM;
        const __nv_bfloat16* ql = g_Ql + (size_t)(b * NTOK + q0) * ADIM;
        #pragma unroll
        for (int i = 0; i < 8; i++) {
            int lin = tid + i * 256;
            int r = lin >> 4, c = lin & 15;
            uint32_t off = (uint32_t)(r * 256 + ((c ^ (r & 7)) << 4));
            size_t g = (size_t)r * ADIM + c * 8;
            cp16(sb + SQH + off, qh + g);
            cp16(sb + SQL + off, ql + g);
        }
    }
    const __nv_bfloat16* KHb = g_Kh + (size_t)b * NTOK * ADIM;
    const __nv_bfloat16* KLb = g_Kl + (size_t)b * NTOK * ADIM;
    const __half* Vb = g_V + (size_t)b * NTOK * ADIM;
    load_kv(sb + SKV, KHb, KLb, Vb, tid);
    cp_commit();
    load_kv(sb + SKV + KVBUF, KHb + 64 * ADIM, KLb + 64 * ADIM, Vb + 64 * ADIM, tid);
    cp_commit();
    cp_wait1();
    __syncthreads();

    float oacc[16][4];
    #pragma unroll
    for (int nb = 0; nb < 16; nb++)
        #pragma unroll
        for (int i = 0; i < 4; i++) oacc[nb][i] = 0.0f;
    float m0 = -CUDART_INF_F, m8 = -CUDART_INF_F, l0 = 0.0f, l8 = 0.0f;

    float sA[8][4], sB[8][4];

    auto s_mma = [&](float (&sacc)[8][4], uint32_t KB) {
        #pragma unroll
        for (int nb = 0; nb < 8; nb++)
            #pragma unroll
            for (int i = 0; i < 4; i++) sacc[nb][i] = 0.0f;
        #pragma unroll
        for (int ks = 0; ks < 8; ks++) {
            uint32_t aqh[4], aql[4];
            uint32_t ach = (uint32_t)(((2 * ks + ca) ^ swa) << 4);
            ldsm4(aqh, sb + SQH + qro + ach);
            ldsm4(aql, sb + SQL + qro + ach);
            uint32_t bch = (uint32_t)(((2 * ks + cb) ^ swb) << 4);
            #pragma unroll
            for (int jp = 0; jp < 4; jp++) {
                uint32_t bh[4], bl[4];
                uint32_t boff = (uint32_t)((16 * jp + rowb) * 256) + bch;
                ldsm4(bh, KB + boff);
                ldsm4(bl, KB + 16384u + boff);
                mma_bf16(sacc[2 * jp],     aqh, bh);
                mma_bf16(sacc[2 * jp + 1], aqh, bh + 2);
                mma_bf16(sacc[2 * jp],     aqh, bl);
                mma_bf16(sacc[2 * jp + 1], aqh, bl + 2);
                mma_bf16(sacc[2 * jp],     aql, bh);
                mma_bf16(sacc[2 * jp + 1], aql, bh + 2);
            }
        }
    };

    auto softmax_pv = [&](float (&sacc)[8][4], uint32_t VB) {
        float rm0 = sacc[0][0], rm8 = sacc[0][2];
        #pragma unroll
        for (int nb = 0; nb < 8; nb++) {
            rm0 = fmaxf(rm0, fmaxf(sacc[nb][0], sacc[nb][1]));
            rm8 = fmaxf(rm8, fmaxf(sacc[nb][2], sacc[nb][3]));
        }
        rm0 = fmaxf(rm0, __shfl_xor_sync(0xffffffffu, rm0, 1));
        rm0 = fmaxf(rm0, __shfl_xor_sync(0xffffffffu, rm0, 2));
        rm8 = fmaxf(rm8, __shfl_xor_sync(0xffffffffu, rm8, 1));
        rm8 = fmaxf(rm8, __shfl_xor_sync(0xffffffffu, rm8, 2));
        float mn0 = fmaxf(m0, rm0), mn8 = fmaxf(m8, rm8);
        float sc0 = ex2(m0 - mn0), sc8 = ex2(m8 - mn8);
        m0 = mn0; m8 = mn8;

        uint32_t ph[8][2];
        float ls0 = 0.0f, ls8 = 0.0f;
        #pragma unroll
        for (int nb = 0; nb < 8; nb++) {
            float p0 = ex2(sacc[nb][0] - mn0);
            float p1 = ex2(sacc[nb][1] - mn0);
            float p2 = ex2(sacc[nb][2] - mn8);
            float p3 = ex2(sacc[nb][3] - mn8);
            ls0 += p0 + p1; ls8 += p2 + p3;
            ph[nb][0] = h2bits(__floats2half2_rn(p0, p1));
            ph[nb][1] = h2bits(__floats2half2_rn(p2, p3));
        }
        l0 = l0 * sc0 + ls0;
        l8 = l8 * sc8 + ls8;
        if (sc0 < 1.0f) {
            #pragma unroll
            for (int nb = 0; nb < 16; nb++) { oacc[nb][0] *= sc0; oacc[nb][1] *= sc0; }
        }
        if (sc8 < 1.0f) {
            #pragma unroll
            for (int nb = 0; nb < 16; nb++) { oacc[nb][2] *= sc8; oacc[nb][3] *= sc8; }
        }

        #pragma unroll
        for (int ks = 0; ks < 4; ks++) {
            uint32_t ah[4] = { ph[2 * ks][0], ph[2 * ks][1], ph[2 * ks + 1][0], ph[2 * ks + 1][1] };
            uint32_t vro = (uint32_t)((16 * ks + rowv) * 256);
            #pragma unroll
            for (int jp = 0; jp < 8; jp++) {
                uint32_t bh[4];
                uint32_t voff = vro + (uint32_t)(((2 * jp + cv) ^ swv) << 4);
                ldsm4t(bh, VB + voff);
                mma_f16(oacc[2 * jp],     ah, bh);
                mma_f16(oacc[2 * jp + 1], ah, bh + 2);
            }
        }
    };

    auto kbuf = [&](int i) { return sb + SKV + (uint32_t)(i % 3) * (uint32_t)KVBUF; };
    auto vbuf = [&](int i) { return sb + SKV + (uint32_t)(i % 3) * (uint32_t)KVBUF + 32768u; };

    s_mma(sA, kbuf(0));

    #pragma unroll 1
    for (int t = 0; t < 64; t += 2) {
        if (t < 63) cp_wait0();
        __syncthreads();
        if (t < 63) s_mma(sB, kbuf(t + 1));
        if (t < 62) {
            size_t o = (size_t)(t + 2) * 64 * ADIM;
            load_kv(kbuf(t + 2), KHb + o, KLb + o, Vb + o, tid);
            cp_commit();
        }
        softmax_pv(sA, vbuf(t));

        const int u = t + 1;
        if (u < 63) cp_wait0();
        __syncthreads();
        if (u < 63) s_mma(sA, kbuf(u + 1));
        if (u < 62) {
            size_t o = (size_t)(u + 2) * 64 * ADIM;
            load_kv(kbuf(u + 2), KHb + o, KLb + o, Vb + o, tid);
            cp_commit();
        }
        softmax_pv(sB, vbuf(u));
    }

    // ---- epilogue ----
    l0 += __shfl_xor_sync(0xffffffffu, l0, 1);
    l0 += __shfl_xor_sync(0xffffffffu, l0, 2);
    l8 += __shfl_xor_sync(0xffffffffu, l8, 1);
    l8 += __shfl_xor_sync(0xffffffffu, l8, 2);
    float inv0 = 1.0f / l0, inv8 = 1.0f / l8;
    size_t r0 = (size_t)b * NTOK + q0 + 16 * w + (lane >> 2);
    int cb2 = 2 * (lane & 3);
    #pragma unroll
    for (int nb = 0; nb < 16; nb++) {
        int c = nb * 8 + cb2;
        __nv_bfloat162 h01, l01, h23, l23;
        split2(oacc[nb][0] * inv0, oacc[nb][1] * inv0, h01, l01);
        split2(oacc[nb][2] * inv8, oacc[nb][3] * inv8, h23, l23);
        *(__nv_bfloat162*)&g_Oh[r0 * ADIM + c] = h01;
        *(__nv_bfloat162*)&g_Ol[r0 * ADIM + c] = l01;
        *(__nv_bfloat162*)&g_Oh[(r0 + 8) * ADIM + c] = h23;
        *(__nv_bfloat162*)&g_Ol[(r0 + 8) * ADIM + c] = l23;
    }
}

// =====================================================================
// Kernel 3: Y = O @ Wo * tanh(relu(1+wg)) via mma.sync, 3xBF16 split.
// grid (128, 2), 256 threads. (unchanged from R12)
// =====================================================================
#define OUT2_AH 0
#define OUT2_AL 16384
#define OUT2_WH 32768
#define OUT2_WL 49152
#define OUT2_SMEM 65536

__global__ __launch_bounds__(256)
void out2_kernel(const float* __restrict__ Wo,
                 const float* __restrict__ wgm, float* __restrict__ Y) {
    extern __shared__ char smc[];
    const uint32_t sb = smem_u32(smc);
    const int tid = threadIdx.x;
    const int w = tid >> 5;
    const int lane = tid & 31;
    const int row0 = blockIdx.x * 128;
    const int col0 = blockIdx.y * 128;

    const int rowa = 16 * w + (lane & 15);
    const int ca = lane >> 4, swa = rowa & 7;
    const int rowv = (lane & 7) + (lane & 8);
    const int cv = (lane >> 4) & 1, swv = rowv & 7;

    float oacc[16][4];
    #pragma unroll
    for (int nb = 0; nb < 16; nb++)
        #pragma unroll
        for (int i = 0; i < 4; i++) oacc[nb][i] = 0.0f;

    #pragma unroll 1
    for (int kc = 0; kc < 2; kc++) {
        __syncthreads();
        #pragma unroll
        for (int i = 0; i < 4; i++) {
            int lin = tid + i * 256;
            int r = lin >> 3, c = lin & 7;
            uint32_t off = (uint32_t)(r * 128 + ((c ^ (r & 7)) << 4));
            size_t g = (size_t)(row0 + r) * ADIM + kc * 64 + c * 8;
            cp16(sb + OUT2_AH + off, g_Oh + g);
            cp16(sb + OUT2_AL + off, g_Ol + g);
        }
        cp_commit();
        #pragma unroll
        for (int i = 0; i < 4; i++) {
            int lin = tid + i * 256;
            int r = lin >> 4, c = lin & 15;
            uint32_t off = (uint32_t)(r * 256 + ((c ^ (r & 7)) << 4));
            split_sts8(&Wo[(size_t)(kc * 64 + r) * CIN + col0 + c * 8],
                       sb + OUT2_WH + off, sb + OUT2_WL + off);
        }
        cp_wait0();
        __syncthreads();
        #pragma unroll
        for (int ks = 0; ks < 4; ks++) {
            uint32_t ah[4], al[4];
            uint32_t ach = (uint32_t)(((2 * ks + ca) ^ swa) << 4);
            ldsm4(ah, sb + OUT2_AH + rowa * 128 + ach);
            ldsm4(al, sb + OUT2_AL + rowa * 128 + ach);
            #pragma unroll
            for (int jp = 0; jp < 8; jp++) {
                uint32_t bh[4], bl[4];
                uint32_t boff = (uint32_t)((16 * ks + rowv) * 256 + (((2 * jp + cv) ^ swv) << 4));
                ldsm4t(bh, sb + OUT2_WH + boff);
                ldsm4t(bl, sb + OUT2_WL + boff);
                mma_bf16(oacc[2 * jp],     ah, bh); mma_bf16(oacc[2 * jp + 1], ah, bh + 2);
                mma_bf16(oacc[2 * jp],     ah, bl); mma_bf16(oacc[2 * jp + 1], ah, bl + 2);
                mma_bf16(oacc[2 * jp],     al, bh); mma_bf16(oacc[2 * jp + 1], al, bh + 2);
            }
        }
    }

    const int r0 = row0 + 16 * w + (lane >> 2);
    const int cb2 = 2 * (lane & 3);
    #pragma unroll
    for (int nb = 0; nb < 16; nb++) {
        int c = col0 + nb * 8 + cb2;
        float g0 = tanhf(fmaxf(1.0f + wgm[c], 0.0f));
        float g1 = tanhf(fmaxf(1.0f + wgm[c + 1], 0.0f));
        *(float2*)&Y[(size_t)r0 * CIN + c] =
            make_float2(oacc[nb][0] * g0, oacc[nb][1] * g1);
        *(float2*)&Y[(size_t)(r0 + 8) * CIN + c] =
            make_float2(oacc[nb][2] * g0, oacc[nb][3] * g1);
    }
}

// =====================================================================
extern "C" void kernel_launch(void* const* d_in, const int* in_sizes, int n_in,
                              void* d_out, int out_size) {
    const float* x  = (const float*)d_in[0];
    const float* Wq = (const float*)d_in[1];
    const float* Wk = (const float*)d_in[2];
    const float* Wv = (const float*)d_in[3];
    const float* Wo = (const float*)d_in[4];
    const float* wg = (const float*)d_in[5];
    float* y = (float*)d_out;

    static bool attrs_set = []() {
        cudaFuncSetAttribute(qkv2_kernel, cudaFuncAttributeMaxDynamicSharedMemorySize, QKV2_SMEM);
        cudaFuncSetAttribute(attn_kernel, cudaFuncAttributeMaxDynamicSharedMemorySize, ATTN_SMEM);
        cudaFuncSetAttribute(out2_kernel, cudaFuncAttributeMaxDynamicSharedMemorySize, OUT2_SMEM);
        return true;
    }();
    (void)attrs_set;

    qkv2_kernel<<<dim3(128, 3), 256, QKV2_SMEM>>>(x, Wq, Wk, Wv);
    attn_kernel<<<dim3(NTOK / 128, BATCH), 256, ATTN_SMEM>>>();
    out2_kernel<<<dim3(128, 2), 256, OUT2_SMEM>>>(Wo, wg, y);
}

// round 14
// speedup vs baseline: 1.0196x; 1.0196x over previous
#include <cuda_runtime.h>
#include <cuda_bf16.h>
#include <cuda_fp16.h>
#include <math_constants.h>
#include <stdint.h>

#define BATCH 4
#define NTOK 4096
#define CIN 256
#define ADIM 128
#define MTOT (BATCH*NTOK)
#define NEG_SLOPE 0.2f
#define LOG2E 1.4426950408889634f

// ---------------- scratch ----------------
__device__ __nv_bfloat16 g_Xh[MTOT * CIN];
__device__ __nv_bfloat16 g_Xl[MTOT * CIN];
__device__ __nv_bfloat16 g_Qh[MTOT * ADIM];   // pre-scaled by log2(e)
__device__ __nv_bfloat16 g_Ql[MTOT * ADIM];
__device__ __nv_bfloat16 g_Kh[MTOT * ADIM];
__device__ __nv_bfloat16 g_Kl[MTOT * ADIM];
__device__ __half        g_V[MTOT * ADIM];
__device__ __nv_bfloat16 g_Oh[MTOT * ADIM];
__device__ __nv_bfloat16 g_Ol[MTOT * ADIM];
__device__ __nv_bfloat16 g_Wqh[CIN * ADIM], g_Wql[CIN * ADIM];
__device__ __nv_bfloat16 g_Wkh[CIN * ADIM], g_Wkl[CIN * ADIM];
__device__ __nv_bfloat16 g_Wvh[CIN * ADIM], g_Wvl[CIN * ADIM];
__device__ __nv_bfloat16 g_Woh[ADIM * CIN], g_Wol[ADIM * CIN];

__device__ __forceinline__ float lrelu(float x) { return x >= 0.0f ? x : NEG_SLOPE * x; }

// ---------------- helpers ----------------
__device__ __forceinline__ uint32_t smem_u32(const void* p) {
    uint32_t a;
    asm("{ .reg .u64 t; cvta.to.shared.u64 t, %1; cvt.u32.u64 %0, t; }" : "=r"(a) : "l"(p));
    return a;
}
__device__ __forceinline__ void cp16(uint32_t dst, const void* src) {
    asm volatile("cp.async.cg.shared.global [%0], [%1], 16;" :: "r"(dst), "l"(src));
}
__device__ __forceinline__ void cp_commit() { asm volatile("cp.async.commit_group;" ::: "memory"); }
__device__ __forceinline__ void cp_wait0() { asm volatile("cp.async.wait_group 0;" ::: "memory"); }
__device__ __forceinline__ void cp_wait1() { asm volatile("cp.async.wait_group 1;" ::: "memory"); }

__device__ __forceinline__ void ldsm4(uint32_t* r, uint32_t a) {
    asm volatile("ldmatrix.sync.aligned.m8n8.x4.shared.b16 {%0,%1,%2,%3}, [%4];"
        : "=r"(r[0]), "=r"(r[1]), "=r"(r[2]), "=r"(r[3]) : "r"(a));
}
__device__ __forceinline__ void ldsm4t(uint32_t* r, uint32_t a) {
    asm volatile("ldmatrix.sync.aligned.m8n8.x4.trans.shared.b16 {%0,%1,%2,%3}, [%4];"
        : "=r"(r[0]), "=r"(r[1]), "=r"(r[2]), "=r"(r[3]) : "r"(a));
}
__device__ __forceinline__ void mma_bf16(float* d, const uint32_t* a, const uint32_t* b) {
    asm volatile(
        "mma.sync.aligned.m16n8k16.row.col.f32.bf16.bf16.f32 "
        "{%0,%1,%2,%3}, {%4,%5,%6,%7}, {%8,%9}, {%0,%1,%2,%3};"
        : "+f"(d[0]), "+f"(d[1]), "+f"(d[2]), "+f"(d[3])
        : "r"(a[0]), "r"(a[1]), "r"(a[2]), "r"(a[3]), "r"(b[0]), "r"(b[1]));
}
__device__ __forceinline__ void mma_f16(float* d, const uint32_t* a, const uint32_t* b) {
    asm volatile(
        "mma.sync.aligned.m16n8k16.row.col.f32.f16.f16.f32 "
        "{%0,%1,%2,%3}, {%4,%5,%6,%7}, {%8,%9}, {%0,%1,%2,%3};"
        : "+f"(d[0]), "+f"(d[1]), "+f"(d[2]), "+f"(d[3])
        : "r"(a[0]), "r"(a[1]), "r"(a[2]), "r"(a[3]), "r"(b[0]), "r"(b[1]));
}
__device__ __forceinline__ uint32_t h2bits(__half2 v) { return *(uint32_t*)&v; }
__device__ __forceinline__ float ex2(float x) {
    float r; asm("ex2.approx.f32 %0, %1;" : "=f"(r) : "f"(x)); return r;
}

__device__ __forceinline__ void split2(float f0, float f1, __nv_bfloat162& h, __nv_bfloat162& l) {
    h = __floats2bfloat162_rn(f0, f1);
    l = __floats2bfloat162_rn(f0 - __bfloat162float(h.x), f1 - __bfloat162float(h.y));
}

// =====================================================================
// Convert kernels: fp32 -> bf16 hi/lo (X once; W once instead of per-CTA)
// =====================================================================
__global__ __launch_bounds__(256)
void convx_kernel(const float* __restrict__ X) {
    int i = blockIdx.x * 256 + threadIdx.x;
    float4 v = ((const float4*)X)[i];
    __nv_bfloat162 h0, l0, h1, l1;
    split2(v.x, v.y, h0, l0);
    split2(v.z, v.w, h1, l1);
    ((__nv_bfloat162*)g_Xh)[2 * i] = h0;
    ((__nv_bfloat162*)g_Xh)[2 * i + 1] = h1;
    ((__nv_bfloat162*)g_Xl)[2 * i] = l0;
    ((__nv_bfloat162*)g_Xl)[2 * i + 1] = l1;
}

__global__ __launch_bounds__(256)
void convw_kernel(const float* __restrict__ Wq, const float* __restrict__ Wk,
                  const float* __restrict__ Wv, const float* __restrict__ Wo) {
    int j = blockIdx.x * 256 + threadIdx.x;
    int sel = j >> 13;
    int loc = j & 8191;
    const float* src = (sel == 0) ? Wq : (sel == 1) ? Wk : (sel == 2) ? Wv : Wo;
    __nv_bfloat16* dh = (sel == 0) ? g_Wqh : (sel == 1) ? g_Wkh : (sel == 2) ? g_Wvh : g_Woh;
    __nv_bfloat16* dl = (sel == 0) ? g_Wql : (sel == 1) ? g_Wkl : (sel == 2) ? g_Wvl : g_Wol;
    float4 v = ((const float4*)src)[loc];
    __nv_bfloat162 h0, l0, h1, l1;
    split2(v.x, v.y, h0, l0);
    split2(v.z, v.w, h1, l1);
    ((__nv_bfloat162*)dh)[2 * loc] = h0;
    ((__nv_bfloat162*)dh)[2 * loc + 1] = h1;
    ((__nv_bfloat162*)dl)[2 * loc] = l0;
    ((__nv_bfloat162*)dl)[2 * loc + 1] = l1;
}

// =====================================================================
// Kernel 1: QKV projection via mma.sync, 3xBF16 split, N=64 per CTA.
// grid (128, 2, 3), 256 threads, 2 CTAs/SM.
// smem per buffer: Xh 16K | Xl 16K | Wh 8K | Wl 8K = 48K; x2 = 96K.
// =====================================================================
#define QKV3_XH 0
#define QKV3_XL 16384
#define QKV3_WH 32768
#define QKV3_WL 40960
#define QKV3_BUF 49152
#define QKV3_SMEM (2*49152)

__global__ __launch_bounds__(256, 2)
void qkv3_kernel() {
    extern __shared__ char smc[];
    const uint32_t sb = smem_u32(smc);
    const int tid = threadIdx.x;
    const int w = tid >> 5;
    const int lane = tid & 31;
    const int row0 = blockIdx.x * 128;
    const int col0 = blockIdx.y * 64;
    const int z = blockIdx.z;

    const __nv_bfloat16* WH = (z == 0) ? g_Wqh : (z == 1) ? g_Wkh : g_Wvh;
    const __nv_bfloat16* WL = (z == 0) ? g_Wql : (z == 1) ? g_Wkl : g_Wvl;

    const int rowa = 16 * w + (lane & 15);
    const int ca = lane >> 4, swa = rowa & 7;
    const int rowv = (lane & 7) + (lane & 8);
    const int cv = (lane >> 4) & 1, swv = rowv & 7;

    auto load = [&](int kc, uint32_t buf) {
        // X chunk [128 rows x 64 k] : 1024 16B-chunks per hi/lo
        #pragma unroll
        for (int i = 0; i < 4; i++) {
            int lin = tid + i * 256;
            int r = lin >> 3, c = lin & 7;
            uint32_t off = (uint32_t)(r * 128 + ((c ^ (r & 7)) << 4));
            size_t g = (size_t)(row0 + r) * CIN + kc * 64 + c * 8;
            cp16(buf + QKV3_XH + off, g_Xh + g);
            cp16(buf + QKV3_XL + off, g_Xl + g);
        }
        // W chunk [64 k x 64 n] : 512 16B-chunks per hi/lo
        #pragma unroll
        for (int i = 0; i < 2; i++) {
            int lin = tid + i * 256;
            int r = lin >> 3, c = lin & 7;
            uint32_t off = (uint32_t)(r * 128 + ((c ^ (r & 7)) << 4));
            size_t g = (size_t)(kc * 64 + r) * ADIM + col0 + c * 8;
            cp16(buf + QKV3_WH + off, WH + g);
            cp16(buf + QKV3_WL + off, WL + g);
        }
    };

    float oacc[8][4];
    #pragma unroll
    for (int nb = 0; nb < 8; nb++)
        #pragma unroll
        for (int i = 0; i < 4; i++) oacc[nb][i] = 0.0f;

    load(0, sb);
    cp_commit();

    #pragma unroll 1
    for (int kc = 0; kc < 4; kc++) {
        __syncthreads();   // prev MMA done before overwriting the other buffer
        if (kc < 3) {
            load(kc + 1, sb + (uint32_t)((kc + 1) & 1) * (uint32_t)QKV3_BUF);
            cp_commit();
            cp_wait1();
        } else {
            cp_wait0();
        }
        __syncthreads();

        const uint32_t buf = sb + (uint32_t)(kc & 1) * (uint32_t)QKV3_BUF;
        #pragma unroll
        for (int ks = 0; ks < 4; ks++) {
            uint32_t ah[4], al[4];
            uint32_t ach = (uint32_t)(((2 * ks + ca) ^ swa) << 4);
            ldsm4(ah, buf + QKV3_XH + rowa * 128 + ach);
            ldsm4(al, buf + QKV3_XL + rowa * 128 + ach);
            #pragma unroll
            for (int jp = 0; jp < 4; jp++) {
                uint32_t bh[4], bl[4];
                uint32_t boff = (uint32_t)((16 * ks + rowv) * 128 + (((2 * jp + cv) ^ swv) << 4));
                ldsm4t(bh, buf + QKV3_WH + boff);
                ldsm4t(bl, buf + QKV3_WL + boff);
                mma_bf16(oacc[2 * jp],     ah, bh); mma_bf16(oacc[2 * jp + 1], ah, bh + 2);
                mma_bf16(oacc[2 * jp],     ah, bl); mma_bf16(oacc[2 * jp + 1], ah, bl + 2);
                mma_bf16(oacc[2 * jp],     al, bh); mma_bf16(oacc[2 * jp + 1], al, bh + 2);
            }
        }
    }

    const int r0 = row0 + 16 * w + (lane >> 2);
    const int cb2 = 2 * (lane & 3);
    if (z == 2) {
        #pragma unroll
        for (int nb = 0; nb < 8; nb++) {
            int c = col0 + nb * 8 + cb2;
            *(__half2*)&g_V[(size_t)r0 * ADIM + c] =
                __floats2half2_rn(lrelu(oacc[nb][0]), lrelu(oacc[nb][1]));
            *(__half2*)&g_V[(size_t)(r0 + 8) * ADIM + c] =
                __floats2half2_rn(lrelu(oacc[nb][2]), lrelu(oacc[nb][3]));
        }
    } else {
        __nv_bfloat16* OH = (z == 0) ? g_Qh : g_Kh;
        __nv_bfloat16* OL = (z == 0) ? g_Ql : g_Kl;
        const float sc = (z == 0) ? LOG2E : 1.0f;
        #pragma unroll
        for (int nb = 0; nb < 8; nb++) {
            int c = col0 + nb * 8 + cb2;
            __nv_bfloat162 h01, l01, h23, l23;
            split2(lrelu(oacc[nb][0]) * sc, lrelu(oacc[nb][1]) * sc, h01, l01);
            split2(lrelu(oacc[nb][2]) * sc, lrelu(oacc[nb][3]) * sc, h23, l23);
            *(__nv_bfloat162*)&OH[(size_t)r0 * ADIM + c] = h01;
            *(__nv_bfloat162*)&OL[(size_t)r0 * ADIM + c] = l01;
            *(__nv_bfloat162*)&OH[(size_t)(r0 + 8) * ADIM + c] = h23;
            *(__nv_bfloat162*)&OL[(size_t)(r0 + 8) * ADIM + c] = l23;
        }
    }
}

// =====================================================================
// Kernel 2: flash attention, software-pipelined with double sacc.
// grid (32,4), 256 threads. (unchanged from R11)
// =====================================================================
#define SQH 0
#define SQL 32768
#define SKV 65536
#define KVBUF 49152
#define ATTN_SMEM (65536 + 3*KVBUF)

__device__ __forceinline__ void load_kv(uint32_t dst, const __nv_bfloat16* kh,
                                        const __nv_bfloat16* kl, const __half* v, int tid) {
    #pragma unroll
    for (int i = 0; i < 4; i++) {
        int lin = tid + i * 256;
        int r = lin >> 4, c = lin & 15;
        uint32_t off = (uint32_t)(r * 256 + ((c ^ (r & 7)) << 4));
        size_t g = (size_t)r * ADIM + c * 8;
        cp16(dst + off, kh + g);
        cp16(dst + 16384 + off, kl + g);
        cp16(dst + 32768 + off, v + g);
    }
}

__global__ __launch_bounds__(256, 1)
void attn_kernel() {
    extern __shared__ char smc[];
    const uint32_t sb = smem_u32(smc);
    const int tid = threadIdx.x;
    const int w = tid >> 5;
    const int lane = tid & 31;
    const int b = blockIdx.y;
    const int q0 = blockIdx.x * 128;

    const int rowa = 16 * w + (lane & 15);
    const uint32_t qro = (uint32_t)rowa * 256;
    const int ca = lane >> 4;
    const int swa = rowa & 7;
    const int rowb = (lane & 7) + ((lane & 16) >> 1);
    const int cb = (lane >> 3) & 1;
    const int swb = rowb & 7;
    const int rowv = (lane & 7) + (lane & 8);
    const int cv = (lane >> 4) & 1;
    const int swv = rowv & 7;

    {
        const __nv_bfloat16* qh = g_Qh + (size_t)(b * NTOK + q0) * ADIM;
        const __nv_bfloat16* ql = g_Ql + (size_t)(b * NTOK + q0) * ADIM;
        #pragma unroll
        for (int i = 0; i < 8; i++) {
            int lin = tid + i * 256;
            int r = lin >> 4, c = lin & 15;
            uint32_t off = (uint32_t)(r * 256 + ((c ^ (r & 7)) << 4));
            size_t g = (size_t)r * ADIM + c * 8;
            cp16(sb + SQH + off, qh + g);
            cp16(sb + SQL + off, ql + g);
        }
    }
    const __nv_bfloat16* KHb = g_Kh + (size_t)b * NTOK * ADIM;
    const __nv_bfloat16* KLb = g_Kl + (size_t)b * NTOK * ADIM;
    const __half* Vb = g_V + (size_t)b * NTOK * ADIM;
    load_kv(sb + SKV, KHb, KLb, Vb, tid);
    cp_commit();
    load_kv(sb + SKV + KVBUF, KHb + 64 * ADIM, KLb + 64 * ADIM, Vb + 64 * ADIM, tid);
    cp_commit();
    cp_wait1();
    __syncthreads();

    float oacc[16][4];
    #pragma unroll
    for (int nb = 0; nb < 16; nb++)
        #pragma unroll
        for (int i = 0; i < 4; i++) oacc[nb][i] = 0.0f;
    float m0 = -CUDART_INF_F, m8 = -CUDART_INF_F, l0 = 0.0f, l8 = 0.0f;

    float sA[8][4], sB[8][4];

    auto s_mma = [&](float (&sacc)[8][4], uint32_t KB) {
        #pragma unroll
        for (int nb = 0; nb < 8; nb++)
            #pragma unroll
            for (int i = 0; i < 4; i++) sacc[nb][i] = 0.0f;
        #pragma unroll
        for (int ks = 0; ks < 8; ks++) {
            uint32_t aqh[4], aql[4];
            uint32_t ach = (uint32_t)(((2 * ks + ca) ^ swa) << 4);
            ldsm4(aqh, sb + SQH + qro + ach);
            ldsm4(aql, sb + SQL + qro + ach);
            uint32_t bch = (uint32_t)(((2 * ks + cb) ^ swb) << 4);
            #pragma unroll
            for (int jp = 0; jp < 4; jp++) {
                uint32_t bh[4], bl[4];
                uint32_t boff = (uint32_t)((16 * jp + rowb) * 256) + bch;
                ldsm4(bh, KB + boff);
                ldsm4(bl, KB + 16384u + boff);
                mma_bf16(sacc[2 * jp],     aqh, bh);
                mma_bf16(sacc[2 * jp + 1], aqh, bh + 2);
                mma_bf16(sacc[2 * jp],     aqh, bl);
                mma_bf16(sacc[2 * jp + 1], aqh, bl + 2);
                mma_bf16(sacc[2 * jp],     aql, bh);
                mma_bf16(sacc[2 * jp + 1], aql, bh + 2);
            }
        }
    };

    auto softmax_pv = [&](float (&sacc)[8][4], uint32_t VB) {
        float rm0 = sacc[0][0], rm8 = sacc[0][2];
        #pragma unroll
        for (int nb = 0; nb < 8; nb++) {
            rm0 = fmaxf(rm0, fmaxf(sacc[nb][0], sacc[nb][1]));
            rm8 = fmaxf(rm8, fmaxf(sacc[nb][2], sacc[nb][3]));
        }
        rm0 = fmaxf(rm0, __shfl_xor_sync(0xffffffffu, rm0, 1));
        rm0 = fmaxf(rm0, __shfl_xor_sync(0xffffffffu, rm0, 2));
        rm8 = fmaxf(rm8, __shfl_xor_sync(0xffffffffu, rm8, 1));
        rm8 = fmaxf(rm8, __shfl_xor_sync(0xffffffffu, rm8, 2));
        float mn0 = fmaxf(m0, rm0), mn8 = fmaxf(m8, rm8);
        float sc0 = ex2(m0 - mn0), sc8 = ex2(m8 - mn8);
        m0 = mn0; m8 = mn8;

        uint32_t ph[8][2];
        float ls0 = 0.0f, ls8 = 0.0f;
        #pragma unroll
        for (int nb = 0; nb < 8; nb++) {
            float p0 = ex2(sacc[nb][0] - mn0);
            float p1 = ex2(sacc[nb][1] - mn0);
            float p2 = ex2(sacc[nb][2] - mn8);
            float p3 = ex2(sacc[nb][3] - mn8);
            ls0 += p0 + p1; ls8 += p2 + p3;
            ph[nb][0] = h2bits(__floats2half2_rn(p0, p1));
            ph[nb][1] = h2bits(__floats2half2_rn(p2, p3));
        }
        l0 = l0 * sc0 + ls0;
        l8 = l8 * sc8 + ls8;
        if (sc0 < 1.0f) {
            #pragma unroll
            for (int nb = 0; nb < 16; nb++) { oacc[nb][0] *= sc0; oacc[nb][1] *= sc0; }
        }
        if (sc8 < 1.0f) {
            #pragma unroll
            for (int nb = 0; nb < 16; nb++) { oacc[nb][2] *= sc8; oacc[nb][3] *= sc8; }
        }

        #pragma unroll
        for (int ks = 0; ks < 4; ks++) {
            uint32_t ah[4] = { ph[2 * ks][0], ph[2 * ks][1], ph[2 * ks + 1][0], ph[2 * ks + 1][1] };
            uint32_t vro = (uint32_t)((16 * ks + rowv) * 256);
            #pragma unroll
            for (int jp = 0; jp < 8; jp++) {
                uint32_t bh[4];
                uint32_t voff = vro + (uint32_t)(((2 * jp + cv) ^ swv) << 4);
                ldsm4t(bh, VB + voff);
                mma_f16(oacc[2 * jp],     ah, bh);
                mma_f16(oacc[2 * jp + 1], ah, bh + 2);
            }
        }
    };

    auto kbuf = [&](int i) { return sb + SKV + (uint32_t)(i % 3) * (uint32_t)KVBUF; };
    auto vbuf = [&](int i) { return sb + SKV + (uint32_t)(i % 3) * (uint32_t)KVBUF + 32768u; };

    s_mma(sA, kbuf(0));

    #pragma unroll 1
    for (int t = 0; t < 64; t += 2) {
        if (t < 63) cp_wait0();
        __syncthreads();
        if (t < 63) s_mma(sB, kbuf(t + 1));
        if (t < 62) {
            size_t o = (size_t)(t + 2) * 64 * ADIM;
            load_kv(kbuf(t + 2), KHb + o, KLb + o, Vb + o, tid);
            cp_commit();
        }
        softmax_pv(sA, vbuf(t));

        const int u = t + 1;
        if (u < 63) cp_wait0();
        __syncthreads();
        if (u < 63) s_mma(sA, kbuf(u + 1));
        if (u < 62) {
            size_t o = (size_t)(u + 2) * 64 * ADIM;
            load_kv(kbuf(u + 2), KHb + o, KLb + o, Vb + o, tid);
            cp_commit();
        }
        softmax_pv(sB, vbuf(u));
    }

    // ---- epilogue ----
    l0 += __shfl_xor_sync(0xffffffffu, l0, 1);
    l0 += __shfl_xor_sync(0xffffffffu, l0, 2);
    l8 += __shfl_xor_sync(0xffffffffu, l8, 1);
    l8 += __shfl_xor_sync(0xffffffffu, l8, 2);
    float inv0 = 1.0f / l0, inv8 = 1.0f / l8;
    size_t r0 = (size_t)b * NTOK + q0 + 16 * w + (lane >> 2);
    int cb2 = 2 * (lane & 3);
    #pragma unroll
    for (int nb = 0; nb < 16; nb++) {
        int c = nb * 8 + cb2;
        __nv_bfloat162 h01, l01, h23, l23;
        split2(oacc[nb][0] * inv0, oacc[nb][1] * inv0, h01, l01);
        split2(oacc[nb][2] * inv8, oacc[nb][3] * inv8, h23, l23);
        *(__nv_bfloat162*)&g_Oh[r0 * ADIM + c] = h01;
        *(__nv_bfloat162*)&g_Ol[r0 * ADIM + c] = l01;
        *(__nv_bfloat162*)&g_Oh[(r0 + 8) * ADIM + c] = h23;
        *(__nv_bfloat162*)&g_Ol[(r0 + 8) * ADIM + c] = l23;
    }
}

// =====================================================================
// Kernel 3: Y = O @ Wo * tanh(relu(1+wg)) via mma.sync, 3xBF16 split.
// grid (128, 2), 256 threads. Wo pre-split, all operands via cp.async.
// =====================================================================
#define OUT2_AH 0
#define OUT2_AL 16384
#define OUT2_WH 32768
#define OUT2_WL 49152
#define OUT2_SMEM 65536

__global__ __launch_bounds__(256)
void out2_kernel(const float* __restrict__ wgm, float* __restrict__ Y) {
    extern __shared__ char smc[];
    const uint32_t sb = smem_u32(smc);
    const int tid = threadIdx.x;
    const int w = tid >> 5;
    const int lane = tid & 31;
    const int row0 = blockIdx.x * 128;
    const int col0 = blockIdx.y * 128;

    const int rowa = 16 * w + (lane & 15);
    const int ca = lane >> 4, swa = rowa & 7;
    const int rowv = (lane & 7) + (lane & 8);
    const int cv = (lane >> 4) & 1, swv = rowv & 7;

    float oacc[16][4];
    #pragma unroll
    for (int nb = 0; nb < 16; nb++)
        #pragma unroll
        for (int i = 0; i < 4; i++) oacc[nb][i] = 0.0f;

    #pragma unroll 1
    for (int kc = 0; kc < 2; kc++) {
        __syncthreads();
        #pragma unroll
        for (int i = 0; i < 4; i++) {
            int lin = tid + i * 256;
            int r = lin >> 3, c = lin & 7;
            uint32_t off = (uint32_t)(r * 128 + ((c ^ (r & 7)) << 4));
            size_t g = (size_t)(row0 + r) * ADIM + kc * 64 + c * 8;
            cp16(sb + OUT2_AH + off, g_Oh + g);
            cp16(sb + OUT2_AL + off, g_Ol + g);
        }
        #pragma unroll
        for (int i = 0; i < 4; i++) {
            int lin = tid + i * 256;
            int r = lin >> 4, c = lin & 15;
            uint32_t off = (uint32_t)(r * 256 + ((c ^ (r & 7)) << 4));
            size_t g = (size_t)(kc * 64 + r) * CIN + col0 + c * 8;
            cp16(sb + OUT2_WH + off, g_Woh + g);
            cp16(sb + OUT2_WL + off, g_Wol + g);
        }
        cp_commit(); cp_wait0();
        __syncthreads();
        #pragma unroll
        for (int ks = 0; ks < 4; ks++) {
            uint32_t ah[4], al[4];
            uint32_t ach = (uint32_t)(((2 * ks + ca) ^ swa) << 4);
            ldsm4(ah, sb + OUT2_AH + rowa * 128 + ach);
            ldsm4(al, sb + OUT2_AL + rowa * 128 + ach);
            #pragma unroll
            for (int jp = 0; jp < 8; jp++) {
                uint32_t bh[4], bl[4];
                uint32_t boff = (uint32_t)((16 * ks + rowv) * 256 + (((2 * jp + cv) ^ swv) << 4));
                ldsm4t(bh, sb + OUT2_WH + boff);
                ldsm4t(bl, sb + OUT2_WL + boff);
                mma_bf16(oacc[2 * jp],     ah, bh); mma_bf16(oacc[2 * jp + 1], ah, bh + 2);
                mma_bf16(oacc[2 * jp],     ah, bl); mma_bf16(oacc[2 * jp + 1], ah, bl + 2);
                mma_bf16(oacc[2 * jp],     al, bh); mma_bf16(oacc[2 * jp + 1], al, bh + 2);
            }
        }
    }

    const int r0 = row0 + 16 * w + (lane >> 2);
    const int cb2 = 2 * (lane & 3);
    #pragma unroll
    for (int nb = 0; nb < 16; nb++) {
        int c = col0 + nb * 8 + cb2;
        float g0 = tanhf(fmaxf(1.0f + wgm[c], 0.0f));
        float g1 = tanhf(fmaxf(1.0f + wgm[c + 1], 0.0f));
        *(float2*)&Y[(size_t)r0 * CIN + c] =
            make_float2(oacc[nb][0] * g0, oacc[nb][1] * g1);
        *(float2*)&Y[(size_t)(r0 + 8) * CIN + c] =
            make_float2(oacc[nb][2] * g0, oacc[nb][3] * g1);
    }
}

// =====================================================================
extern "C" void kernel_launch(void* const* d_in, const int* in_sizes, int n_in,
                              void* d_out, int out_size) {
    const float* x  = (const float*)d_in[0];
    const float* Wq = (const float*)d_in[1];
    const float* Wk = (const float*)d_in[2];
    const float* Wv = (const float*)d_in[3];
    const float* Wo = (const float*)d_in[4];
    const float* wg = (const float*)d_in[5];
    float* y = (float*)d_out;

    static bool attrs_set = []() {
        cudaFuncSetAttribute(qkv3_kernel, cudaFuncAttributeMaxDynamicSharedMemorySize, QKV3_SMEM);
        cudaFuncSetAttribute(attn_kernel, cudaFuncAttributeMaxDynamicSharedMemorySize, ATTN_SMEM);
        cudaFuncSetAttribute(out2_kernel, cudaFuncAttributeMaxDynamicSharedMemorySize, OUT2_SMEM);
        return true;
    }();
    (void)attrs_set;

    convx_kernel<<<4096, 256>>>(x);
    convw_kernel<<<128, 256>>>(Wq, Wk, Wv, Wo);
    qkv3_kernel<<<dim3(128, 2, 3), 256, QKV3_SMEM>>>();
    attn_kernel<<<dim3(NTOK / 128, BATCH), 256, ATTN_SMEM>>>();
    out2_kernel<<<dim3(128, 2), 256, OUT2_SMEM>>>(wg, y);
}

// round 16
// speedup vs baseline: 1.0284x; 1.0086x over previous
#include <cuda_runtime.h>
#include <cuda_bf16.h>
#include <cuda_fp16.h>
#include <math_constants.h>
#include <stdint.h>

#define BATCH 4
#define NTOK 4096
#define CIN 256
#define ADIM 128
#define MTOT (BATCH*NTOK)
#define NEG_SLOPE 0.2f
#define LOG2E 1.4426950408889634f

// ---------------- scratch ----------------
__device__ __nv_bfloat16 g_Xh[MTOT * CIN];
__device__ __nv_bfloat16 g_Xl[MTOT * CIN];
__device__ __nv_bfloat16 g_Qh[MTOT * ADIM];   // pre-scaled by log2(e)
__device__ __nv_bfloat16 g_Ql[MTOT * ADIM];
__device__ __nv_bfloat16 g_Kh[MTOT * ADIM];
__device__ __nv_bfloat16 g_Kl[MTOT * ADIM];
__device__ __half        g_V[MTOT * ADIM];
__device__ __nv_bfloat16 g_Oh[MTOT * ADIM];
__device__ __nv_bfloat16 g_Ol[MTOT * ADIM];
__device__ __nv_bfloat16 g_Wqh[CIN * ADIM], g_Wql[CIN * ADIM];
__device__ __nv_bfloat16 g_Wkh[CIN * ADIM], g_Wkl[CIN * ADIM];
__device__ __nv_bfloat16 g_Wvh[CIN * ADIM], g_Wvl[CIN * ADIM];
__device__ __nv_bfloat16 g_Woh[ADIM * CIN], g_Wol[ADIM * CIN];

__device__ __forceinline__ float lrelu(float x) { return x >= 0.0f ? x : NEG_SLOPE * x; }

// ---------------- helpers ----------------
__device__ __forceinline__ uint32_t smem_u32(const void* p) {
    uint32_t a;
    asm("{ .reg .u64 t; cvta.to.shared.u64 t, %1; cvt.u32.u64 %0, t; }" : "=r"(a) : "l"(p));
    return a;
}
__device__ __forceinline__ void cp16(uint32_t dst, const void* src) {
    asm volatile("cp.async.cg.shared.global [%0], [%1], 16;" :: "r"(dst), "l"(src));
}
__device__ __forceinline__ void cp_commit() { asm volatile("cp.async.commit_group;" ::: "memory"); }
__device__ __forceinline__ void cp_wait0() { asm volatile("cp.async.wait_group 0;" ::: "memory"); }
__device__ __forceinline__ void cp_wait1() { asm volatile("cp.async.wait_group 1;" ::: "memory"); }

__device__ __forceinline__ void ldsm4(uint32_t* r, uint32_t a) {
    asm volatile("ldmatrix.sync.aligned.m8n8.x4.shared.b16 {%0,%1,%2,%3}, [%4];"
        : "=r"(r[0]), "=r"(r[1]), "=r"(r[2]), "=r"(r[3]) : "r"(a));
}
__device__ __forceinline__ void ldsm4t(uint32_t* r, uint32_t a) {
    asm volatile("ldmatrix.sync.aligned.m8n8.x4.trans.shared.b16 {%0,%1,%2,%3}, [%4];"
        : "=r"(r[0]), "=r"(r[1]), "=r"(r[2]), "=r"(r[3]) : "r"(a));
}
__device__ __forceinline__ void mma_bf16(float* d, const uint32_t* a, const uint32_t* b) {
    asm volatile(
        "mma.sync.aligned.m16n8k16.row.col.f32.bf16.bf16.f32 "
        "{%0,%1,%2,%3}, {%4,%5,%6,%7}, {%8,%9}, {%0,%1,%2,%3};"
        : "+f"(d[0]), "+f"(d[1]), "+f"(d[2]), "+f"(d[3])
        : "r"(a[0]), "r"(a[1]), "r"(a[2]), "r"(a[3]), "r"(b[0]), "r"(b[1]));
}
__device__ __forceinline__ void mma_f16(float* d, const uint32_t* a, const uint32_t* b) {
    asm volatile(
        "mma.sync.aligned.m16n8k16.row.col.f32.f16.f16.f32 "
        "{%0,%1,%2,%3}, {%4,%5,%6,%7}, {%8,%9}, {%0,%1,%2,%3};"
        : "+f"(d[0]), "+f"(d[1]), "+f"(d[2]), "+f"(d[3])
        : "r"(a[0]), "r"(a[1]), "r"(a[2]), "r"(a[3]), "r"(b[0]), "r"(b[1]));
}
__device__ __forceinline__ uint32_t h2bits(__half2 v) { return *(uint32_t*)&v; }
__device__ __forceinline__ float ex2(float x) {
    float r; asm("ex2.approx.f32 %0, %1;" : "=f"(r) : "f"(x)); return r;
}

__device__ __forceinline__ void split2(float f0, float f1, __nv_bfloat162& h, __nv_bfloat162& l) {
    h = __floats2bfloat162_rn(f0, f1);
    l = __floats2bfloat162_rn(f0 - __bfloat162float(h.x), f1 - __bfloat162float(h.y));
}

// =====================================================================
// Fused convert kernel: blocks [0,4096) split X; [4096,4224) split W.
// =====================================================================
__global__ __launch_bounds__(256)
void conv_kernel(const float* __restrict__ X,
                 const float* __restrict__ Wq, const float* __restrict__ Wk,
                 const float* __restrict__ Wv, const float* __restrict__ Wo) {
    if (blockIdx.x < 4096) {
        int i = blockIdx.x * 256 + threadIdx.x;
        float4 v = ((const float4*)X)[i];
        __nv_bfloat162 h0, l0, h1, l1;
        split2(v.x, v.y, h0, l0);
        split2(v.z, v.w, h1, l1);
        ((__nv_bfloat162*)g_Xh)[2 * i] = h0;
        ((__nv_bfloat162*)g_Xh)[2 * i + 1] = h1;
        ((__nv_bfloat162*)g_Xl)[2 * i] = l0;
        ((__nv_bfloat162*)g_Xl)[2 * i + 1] = l1;
    } else {
        int j = (blockIdx.x - 4096) * 256 + threadIdx.x;
        int sel = j >> 13;
        int loc = j & 8191;
        const float* src = (sel == 0) ? Wq : (sel == 1) ? Wk : (sel == 2) ? Wv : Wo;
        __nv_bfloat16* dh = (sel == 0) ? g_Wqh : (sel == 1) ? g_Wkh : (sel == 2) ? g_Wvh : g_Woh;
        __nv_bfloat16* dl = (sel == 0) ? g_Wql : (sel == 1) ? g_Wkl : (sel == 2) ? g_Wvl : g_Wol;
        float4 v = ((const float4*)src)[loc];
        __nv_bfloat162 h0, l0, h1, l1;
        split2(v.x, v.y, h0, l0);
        split2(v.z, v.w, h1, l1);
        ((__nv_bfloat162*)dh)[2 * loc] = h0;
        ((__nv_bfloat162*)dh)[2 * loc + 1] = h1;
        ((__nv_bfloat162*)dl)[2 * loc] = l0;
        ((__nv_bfloat162*)dl)[2 * loc + 1] = l1;
    }
}

// =====================================================================
// Kernel 1: QKV projection via mma.sync, 3xBF16 split, N=64 per CTA.
// grid (128, 2, 3), 256 threads, 2 CTAs/SM.
// =====================================================================
#define QKV3_XH 0
#define QKV3_XL 16384
#define QKV3_WH 32768
#define QKV3_WL 40960
#define QKV3_BUF 49152
#define QKV3_SMEM (2*49152)

__global__ __launch_bounds__(256, 2)
void qkv3_kernel() {
    extern __shared__ char smc[];
    const uint32_t sb = smem_u32(smc);
    const int tid = threadIdx.x;
    const int w = tid >> 5;
    const int lane = tid & 31;
    const int row0 = blockIdx.x * 128;
    const int col0 = blockIdx.y * 64;
    const int z = blockIdx.z;

    const __nv_bfloat16* WH = (z == 0) ? g_Wqh : (z == 1) ? g_Wkh : g_Wvh;
    const __nv_bfloat16* WL = (z == 0) ? g_Wql : (z == 1) ? g_Wkl : g_Wvl;

    const int rowa = 16 * w + (lane & 15);
    const int ca = lane >> 4, swa = rowa & 7;
    const int rowv = (lane & 7) + (lane & 8);
    const int cv = (lane >> 4) & 1, swv = rowv & 7;

    auto load = [&](int kc, uint32_t buf) {
        #pragma unroll
        for (int i = 0; i < 4; i++) {
            int lin = tid + i * 256;
            int r = lin >> 3, c = lin & 7;
            uint32_t off = (uint32_t)(r * 128 + ((c ^ (r & 7)) << 4));
            size_t g = (size_t)(row0 + r) * CIN + kc * 64 + c * 8;
            cp16(buf + QKV3_XH + off, g_Xh + g);
            cp16(buf + QKV3_XL + off, g_Xl + g);
        }
        #pragma unroll
        for (int i = 0; i < 2; i++) {
            int lin = tid + i * 256;
            int r = lin >> 3, c = lin & 7;
            uint32_t off = (uint32_t)(r * 128 + ((c ^ (r & 7)) << 4));
            size_t g = (size_t)(kc * 64 + r) * ADIM + col0 + c * 8;
            cp16(buf + QKV3_WH + off, WH + g);
            cp16(buf + QKV3_WL + off, WL + g);
        }
    };

    float oacc[8][4];
    #pragma unroll
    for (int nb = 0; nb < 8; nb++)
        #pragma unroll
        for (int i = 0; i < 4; i++) oacc[nb][i] = 0.0f;

    load(0, sb);
    cp_commit();

    #pragma unroll 1
    for (int kc = 0; kc < 4; kc++) {
        __syncthreads();
        if (kc < 3) {
            load(kc + 1, sb + (uint32_t)((kc + 1) & 1) * (uint32_t)QKV3_BUF);
            cp_commit();
            cp_wait1();
        } else {
            cp_wait0();
        }
        __syncthreads();

        const uint32_t buf = sb + (uint32_t)(kc & 1) * (uint32_t)QKV3_BUF;
        #pragma unroll
        for (int ks = 0; ks < 4; ks++) {
            uint32_t ah[4], al[4];
            uint32_t ach = (uint32_t)(((2 * ks + ca) ^ swa) << 4);
            ldsm4(ah, buf + QKV3_XH + rowa * 128 + ach);
            ldsm4(al, buf + QKV3_XL + rowa * 128 + ach);
            #pragma unroll
            for (int jp = 0; jp < 4; jp++) {
                uint32_t bh[4], bl[4];
                uint32_t boff = (uint32_t)((16 * ks + rowv) * 128 + (((2 * jp + cv) ^ swv) << 4));
                ldsm4t(bh, buf + QKV3_WH + boff);
                ldsm4t(bl, buf + QKV3_WL + boff);
                mma_bf16(oacc[2 * jp],     ah, bh); mma_bf16(oacc[2 * jp + 1], ah, bh + 2);
                mma_bf16(oacc[2 * jp],     ah, bl); mma_bf16(oacc[2 * jp + 1], ah, bl + 2);
                mma_bf16(oacc[2 * jp],     al, bh); mma_bf16(oacc[2 * jp + 1], al, bh + 2);
            }
        }
    }

    const int r0 = row0 + 16 * w + (lane >> 2);
    const int cb2 = 2 * (lane & 3);
    if (z == 2) {
        #pragma unroll
        for (int nb = 0; nb < 8; nb++) {
            int c = col0 + nb * 8 + cb2;
            *(__half2*)&g_V[(size_t)r0 * ADIM + c] =
                __floats2half2_rn(lrelu(oacc[nb][0]), lrelu(oacc[nb][1]));
            *(__half2*)&g_V[(size_t)(r0 + 8) * ADIM + c] =
                __floats2half2_rn(lrelu(oacc[nb][2]), lrelu(oacc[nb][3]));
        }
    } else {
        __nv_bfloat16* OH = (z == 0) ? g_Qh : g_Kh;
        __nv_bfloat16* OL = (z == 0) ? g_Ql : g_Kl;
        const float sc = (z == 0) ? LOG2E : 1.0f;
        #pragma unroll
        for (int nb = 0; nb < 8; nb++) {
            int c = col0 + nb * 8 + cb2;
            __nv_bfloat162 h01, l01, h23, l23;
            split2(lrelu(oacc[nb][0]) * sc, lrelu(oacc[nb][1]) * sc, h01, l01);
            split2(lrelu(oacc[nb][2]) * sc, lrelu(oacc[nb][3]) * sc, h23, l23);
            *(__nv_bfloat162*)&OH[(size_t)r0 * ADIM + c] = h01;
            *(__nv_bfloat162*)&OL[(size_t)r0 * ADIM + c] = l01;
            *(__nv_bfloat162*)&OH[(size_t)(r0 + 8) * ADIM + c] = h23;
            *(__nv_bfloat162*)&OL[(size_t)(r0 + 8) * ADIM + c] = l23;
        }
    }
}

// =====================================================================
// Kernel 2: flash attention, software-pipelined with double sacc.
// grid (32,4), 256 threads. (unchanged from R11)
// =====================================================================
#define SQH 0
#define SQL 32768
#define SKV 65536
#define KVBUF 49152
#define ATTN_SMEM (65536 + 3*KVBUF)

__device__ __forceinline__ void load_kv(uint32_t dst, const __nv_bfloat16* kh,
                                        const __nv_bfloat16* kl, const __half* v, int tid) {
    #pragma unroll
    for (int i = 0; i < 4; i++) {
        int lin = tid + i * 256;
        int r = lin >> 4, c = lin & 15;
        uint32_t off = (uint32_t)(r * 256 + ((c ^ (r & 7)) << 4));
        size_t g = (size_t)r * ADIM + c * 8;
        cp16(dst + off, kh + g);
        cp16(dst + 16384 + off, kl + g);
        cp16(dst + 32768 + off, v + g);
    }
}

__global__ __launch_bounds__(256, 1)
void attn_kernel() {
    extern __shared__ char smc[];
    const uint32_t sb = smem_u32(smc);
    const int tid = threadIdx.x;
    const int w = tid >> 5;
    const int lane = tid & 31;
    const int b = blockIdx.y;
    const int q0 = blockIdx.x * 128;

    const int rowa = 16 * w + (lane & 15);
    const uint32_t qro = (uint32_t)rowa * 256;
    const int ca = lane >> 4;
    const int swa = rowa & 7;
    const int rowb = (lane & 7) + ((lane & 16) >> 1);
    const int cb = (lane >> 3) & 1;
    const int swb = rowb & 7;
    const int rowv = (lane & 7) + (lane & 8);
    const int cv = (lane >> 4) & 1;
    const int swv = rowv & 7;

    {
        const __nv_bfloat16* qh = g_Qh + (size_t)(b * NTOK + q0) * ADIM;
        const __nv_bfloat16* ql = g_Ql + (size_t)(b * NTOK + q0) * ADIM;
        #pragma unroll
        for (int i = 0; i < 8; i++) {
            int lin = tid + i * 256;
            int r = lin >> 4, c = lin & 15;
            uint32_t off = (uint32_t)(r * 256 + ((c ^ (r & 7)) << 4));
            size_t g = (size_t)r * ADIM + c * 8;
            cp16(sb + SQH + off, qh + g);
            cp16(sb + SQL + off, ql + g);
        }
    }
    const __nv_bfloat16* KHb = g_Kh + (size_t)b * NTOK * ADIM;
    const __nv_bfloat16* KLb = g_Kl + (size_t)b * NTOK * ADIM;
    const __half* Vb = g_V + (size_t)b * NTOK * ADIM;
    load_kv(sb + SKV, KHb, KLb, Vb, tid);
    cp_commit();
    load_kv(sb + SKV + KVBUF, KHb + 64 * ADIM, KLb + 64 * ADIM, Vb + 64 * ADIM, tid);
    cp_commit();
    cp_wait1();
    __syncthreads();

    float oacc[16][4];
    #pragma unroll
    for (int nb = 0; nb < 16; nb++)
        #pragma unroll
        for (int i = 0; i < 4; i++) oacc[nb][i] = 0.0f;
    float m0 = -CUDART_INF_F, m8 = -CUDART_INF_F, l0 = 0.0f, l8 = 0.0f;

    float sA[8][4], sB[8][4];

    auto s_mma = [&](float (&sacc)[8][4], uint32_t KB) {
        #pragma unroll
        for (int nb = 0; nb < 8; nb++)
            #pragma unroll
            for (int i = 0; i < 4; i++) sacc[nb][i] = 0.0f;
        #pragma unroll
        for (int ks = 0; ks < 8; ks++) {
            uint32_t aqh[4], aql[4];
            uint32_t ach = (uint32_t)(((2 * ks + ca) ^ swa) << 4);
            ldsm4(aqh, sb + SQH + qro + ach);
            ldsm4(aql, sb + SQL + qro + ach);
            uint32_t bch = (uint32_t)(((2 * ks + cb) ^ swb) << 4);
            #pragma unroll
            for (int jp = 0; jp < 4; jp++) {
                uint32_t bh[4], bl[4];
                uint32_t boff = (uint32_t)((16 * jp + rowb) * 256) + bch;
                ldsm4(bh, KB + boff);
                ldsm4(bl, KB + 16384u + boff);
                mma_bf16(sacc[2 * jp],     aqh, bh);
                mma_bf16(sacc[2 * jp + 1], aqh, bh + 2);
                mma_bf16(sacc[2 * jp],     aqh, bl);
                mma_bf16(sacc[2 * jp + 1], aqh, bl + 2);
                mma_bf16(sacc[2 * jp],     aql, bh);
                mma_bf16(sacc[2 * jp + 1], aql, bh + 2);
            }
        }
    };

    auto softmax_pv = [&](float (&sacc)[8][4], uint32_t VB) {
        float rm0 = sacc[0][0], rm8 = sacc[0][2];
        #pragma unroll
        for (int nb = 0; nb < 8; nb++) {
            rm0 = fmaxf(rm0, fmaxf(sacc[nb][0], sacc[nb][1]));
            rm8 = fmaxf(rm8, fmaxf(sacc[nb][2], sacc[nb][3]));
        }
        rm0 = fmaxf(rm0, __shfl_xor_sync(0xffffffffu, rm0, 1));
        rm0 = fmaxf(rm0, __shfl_xor_sync(0xffffffffu, rm0, 2));
        rm8 = fmaxf(rm8, __shfl_xor_sync(0xffffffffu, rm8, 1));
        rm8 = fmaxf(rm8, __shfl_xor_sync(0xffffffffu, rm8, 2));
        float mn0 = fmaxf(m0, rm0), mn8 = fmaxf(m8, rm8);
        float sc0 = ex2(m0 - mn0), sc8 = ex2(m8 - mn8);
        m0 = mn0; m8 = mn8;

        uint32_t ph[8][2];
        float ls0 = 0.0f, ls8 = 0.0f;
        #pragma unroll
        for (int nb = 0; nb < 8; nb++) {
            float p0 = ex2(sacc[nb][0] - mn0);
            float p1 = ex2(sacc[nb][1] - mn0);
            float p2 = ex2(sacc[nb][2] - mn8);
            float p3 = ex2(sacc[nb][3] - mn8);
            ls0 += p0 + p1; ls8 += p2 + p3;
            ph[nb][0] = h2bits(__floats2half2_rn(p0, p1));
            ph[nb][1] = h2bits(__floats2half2_rn(p2, p3));
        }
        l0 = l0 * sc0 + ls0;
        l8 = l8 * sc8 + ls8;
        if (sc0 < 1.0f) {
            #pragma unroll
            for (int nb = 0; nb < 16; nb++) { oacc[nb][0] *= sc0; oacc[nb][1] *= sc0; }
        }
        if (sc8 < 1.0f) {
            #pragma unroll
            for (int nb = 0; nb < 16; nb++) { oacc[nb][2] *= sc8; oacc[nb][3] *= sc8; }
        }

        #pragma unroll
        for (int ks = 0; ks < 4; ks++) {
            uint32_t ah[4] = { ph[2 * ks][0], ph[2 * ks][1], ph[2 * ks + 1][0], ph[2 * ks + 1][1] };
            uint32_t vro = (uint32_t)((16 * ks + rowv) * 256);
            #pragma unroll
            for (int jp = 0; jp < 8; jp++) {
                uint32_t bh[4];
                uint32_t voff = vro + (uint32_t)(((2 * jp + cv) ^ swv) << 4);
                ldsm4t(bh, VB + voff);
                mma_f16(oacc[2 * jp],     ah, bh);
                mma_f16(oacc[2 * jp + 1], ah, bh + 2);
            }
        }
    };

    auto kbuf = [&](int i) { return sb + SKV + (uint32_t)(i % 3) * (uint32_t)KVBUF; };
    auto vbuf = [&](int i) { return sb + SKV + (uint32_t)(i % 3) * (uint32_t)KVBUF + 32768u; };

    s_mma(sA, kbuf(0));

    #pragma unroll 1
    for (int t = 0; t < 64; t += 2) {
        if (t < 63) cp_wait0();
        __syncthreads();
        if (t < 63) s_mma(sB, kbuf(t + 1));
        if (t < 62) {
            size_t o = (size_t)(t + 2) * 64 * ADIM;
            load_kv(kbuf(t + 2), KHb + o, KLb + o, Vb + o, tid);
            cp_commit();
        }
        softmax_pv(sA, vbuf(t));

        const int u = t + 1;
        if (u < 63) cp_wait0();
        __syncthreads();
        if (u < 63) s_mma(sA, kbuf(u + 1));
        if (u < 62) {
            size_t o = (size_t)(u + 2) * 64 * ADIM;
            load_kv(kbuf(u + 2), KHb + o, KLb + o, Vb + o, tid);
            cp_commit();
        }
        softmax_pv(sB, vbuf(u));
    }

    // ---- epilogue ----
    l0 += __shfl_xor_sync(0xffffffffu, l0, 1);
    l0 += __shfl_xor_sync(0xffffffffu, l0, 2);
    l8 += __shfl_xor_sync(0xffffffffu, l8, 1);
    l8 += __shfl_xor_sync(0xffffffffu, l8, 2);
    float inv0 = 1.0f / l0, inv8 = 1.0f / l8;
    size_t r0 = (size_t)b * NTOK + q0 + 16 * w + (lane >> 2);
    int cb2 = 2 * (lane & 3);
    #pragma unroll
    for (int nb = 0; nb < 16; nb++) {
        int c = nb * 8 + cb2;
        __nv_bfloat162 h01, l01, h23, l23;
        split2(oacc[nb][0] * inv0, oacc[nb][1] * inv0, h01, l01);
        split2(oacc[nb][2] * inv8, oacc[nb][3] * inv8, h23, l23);
        *(__nv_bfloat162*)&g_Oh[r0 * ADIM + c] = h01;
        *(__nv_bfloat162*)&g_Ol[r0 * ADIM + c] = l01;
        *(__nv_bfloat162*)&g_Oh[(r0 + 8) * ADIM + c] = h23;
        *(__nv_bfloat162*)&g_Ol[(r0 + 8) * ADIM + c] = l23;
    }
}

// =====================================================================
// Kernel 3: Y = O @ Wo * tanh(relu(1+wg)) via mma.sync, 3xBF16 split.
// grid (128, 4), 256 threads, N=64 per CTA, 2 CTAs/SM, double-buffered.
// =====================================================================
#define OUT3_AH 0
#define OUT3_AL 16384
#define OUT3_WH 32768
#define OUT3_WL 40960
#define OUT3_BUF 49152
#define OUT3_SMEM (2*49152)

__global__ __launch_bounds__(256, 2)
void out3_kernel(const float* __restrict__ wgm, float* __restrict__ Y) {
    extern __shared__ char smc[];
    const uint32_t sb = smem_u32(smc);
    const int tid = threadIdx.x;
    const int w = tid >> 5;
    const int lane = tid & 31;
    const int row0 = blockIdx.x * 128;
    const int col0 = blockIdx.y * 64;

    const int rowa = 16 * w + (lane & 15);
    const int ca = lane >> 4, swa = rowa & 7;
    const int rowv = (lane & 7) + (lane & 8);
    const int cv = (lane >> 4) & 1, swv = rowv & 7;

    auto load = [&](int kc, uint32_t buf) {
        #pragma unroll
        for (int i = 0; i < 4; i++) {
            int lin = tid + i * 256;
            int r = lin >> 3, c = lin & 7;
            uint32_t off = (uint32_t)(r * 128 + ((c ^ (r & 7)) << 4));
            size_t g = (size_t)(row0 + r) * ADIM + kc * 64 + c * 8;
            cp16(buf + OUT3_AH + off, g_Oh + g);
            cp16(buf + OUT3_AL + off, g_Ol + g);
        }
        #pragma unroll
        for (int i = 0; i < 2; i++) {
            int lin = tid + i * 256;
            int r = lin >> 3, c = lin & 7;
            uint32_t off = (uint32_t)(r * 128 + ((c ^ (r & 7)) << 4));
            size_t g = (size_t)(kc * 64 + r) * CIN + col0 + c * 8;
            cp16(buf + OUT3_WH + off, g_Woh + g);
            cp16(buf + OUT3_WL + off, g_Wol + g);
        }
    };

    float oacc[8][4];
    #pragma unroll
    for (int nb = 0; nb < 8; nb++)
        #pragma unroll
        for (int i = 0; i < 4; i++) oacc[nb][i] = 0.0f;

    load(0, sb);
    cp_commit();

    #pragma unroll 1
    for (int kc = 0; kc < 2; kc++) {
        __syncthreads();
        if (kc < 1) {
            load(kc + 1, sb + (uint32_t)(((kc + 1) & 1) * OUT3_BUF));
            cp_commit();
            cp_wait1();
        } else {
            cp_wait0();
        }
        __syncthreads();

        const uint32_t buf = sb + (uint32_t)(kc & 1) * (uint32_t)OUT3_BUF;
        #pragma unroll
        for (int ks = 0; ks < 4; ks++) {
            uint32_t ah[4], al[4];
            uint32_t ach = (uint32_t)(((2 * ks + ca) ^ swa) << 4);
            ldsm4(ah, buf + OUT3_AH + rowa * 128 + ach);
            ldsm4(al, buf + OUT3_AL + rowa * 128 + ach);
            #pragma unroll
            for (int jp = 0; jp < 4; jp++) {
                uint32_t bh[4], bl[4];
                uint32_t boff = (uint32_t)((16 * ks + rowv) * 128 + (((2 * jp + cv) ^ swv) << 4));
                ldsm4t(bh, buf + OUT3_WH + boff);
                ldsm4t(bl, buf + OUT3_WL + boff);
                mma_bf16(oacc[2 * jp],     ah, bh); mma_bf16(oacc[2 * jp + 1], ah, bh + 2);
                mma_bf16(oacc[2 * jp],     ah, bl); mma_bf16(oacc[2 * jp + 1], ah, bl + 2);
                mma_bf16(oacc[2 * jp],     al, bh); mma_bf16(oacc[2 * jp + 1], al, bh + 2);
            }
        }
    }

    const int r0 = row0 + 16 * w + (lane >> 2);
    const int cb2 = 2 * (lane & 3);
    #pragma unroll
    for (int nb = 0; nb < 8; nb++) {
        int c = col0 + nb * 8 + cb2;
        float g0 = tanhf(fmaxf(1.0f + wgm[c], 0.0f));
        float g1 = tanhf(fmaxf(1.0f + wgm[c + 1], 0.0f));
        *(float2*)&Y[(size_t)r0 * CIN + c] =
            make_float2(oacc[nb][0] * g0, oacc[nb][1] * g1);
        *(float2*)&Y[(size_t)(r0 + 8) * CIN + c] =
            make_float2(oacc[nb][2] * g0, oacc[nb][3] * g1);
    }
}

// =====================================================================
extern "C" void kernel_launch(void* const* d_in, const int* in_sizes, int n_in,
                              void* d_out, int out_size) {
    const float* x  = (const float*)d_in[0];
    const float* Wq = (const float*)d_in[1];
    const float* Wk = (const float*)d_in[2];
    const float* Wv = (const float*)d_in[3];
    const float* Wo = (const float*)d_in[4];
    const float* wg = (const float*)d_in[5];
    float* y = (float*)d_out;

    static bool attrs_set = []() {
        cudaFuncSetAttribute(qkv3_kernel, cudaFuncAttributeMaxDynamicSharedMemorySize, QKV3_SMEM);
        cudaFuncSetAttribute(attn_kernel, cudaFuncAttributeMaxDynamicSharedMemorySize, ATTN_SMEM);
        cudaFuncSetAttribute(out3_kernel, cudaFuncAttributeMaxDynamicSharedMemorySize, OUT3_SMEM);
        return true;
    }();
    (void)attrs_set;

    conv_kernel<<<4224, 256>>>(x, Wq, Wk, Wv, Wo);
    qkv3_kernel<<<dim3(128, 2, 3), 256, QKV3_SMEM>>>();
    attn_kernel<<<dim3(NTOK / 128, BATCH), 256, ATTN_SMEM>>>();
    out3_kernel<<<dim3(128, 4), 256, OUT3_SMEM>>>(wg, y);
}